// round 8
// baseline (speedup 1.0000x reference)
#include <cuda_runtime.h>
#include <cuda_bf16.h>
#include <math.h>
#include <stdint.h>

#define N_NODESC 50000
#define N_EDGESC 640000
#define N_GRAPHSC 64
#define HC 128
#define AS 136      // A tile stride in halves
#define PSTRIDE 132 // pool tile stride in floats
typedef unsigned long long ull;

__device__ __align__(16) int   g_deg[N_NODESC];
__device__ __align__(16) int   g_off[N_NODESC + 1];
__device__ __align__(16) int   g_pos[N_NODESC];
__device__ __align__(16) int   g_srcs[N_EDGESC];
__device__ __align__(16) float g_h1[N_NODESC * HC];
__device__ __align__(16) float g_h2[N_NODESC * HC];
__device__ __align__(16) float g_pooled[N_GRAPHSC * 3 * HC];
__device__ __align__(16) uint2 g_wpack[10][4096];   // 5 weights x {hi,lo}, fragment-ordered

// ---------------- helpers ----------------
__device__ __forceinline__ void bsplit(float v, unsigned short& h, unsigned short& l) {
    __nv_bfloat16 bh = __float2bfloat16(v);
    h = __bfloat16_as_ushort(bh);
    l = __bfloat16_as_ushort(__float2bfloat16(v - __bfloat162float(bh)));
}
__device__ __forceinline__ void mma_bf16(float* c, uint32_t a0, uint32_t a1, uint32_t a2,
                                         uint32_t a3, uint32_t b0, uint32_t b1) {
    asm volatile("mma.sync.aligned.m16n8k16.row.col.f32.bf16.bf16.f32 "
                 "{%0,%1,%2,%3}, {%4,%5,%6,%7}, {%8,%9}, {%0,%1,%2,%3};"
                 : "+f"(c[0]), "+f"(c[1]), "+f"(c[2]), "+f"(c[3])
                 : "r"(a0), "r"(a1), "r"(a2), "r"(a3), "r"(b0), "r"(b1));
}
__device__ __forceinline__ ull pack2(float x, float y) { ull r; asm("mov.b64 %0, {%1, %2};" : "=l"(r) : "f"(x), "f"(y)); return r; }
__device__ __forceinline__ void ffma2(ull& d, ull a, ull b) { asm("fma.rn.f32x2 %0, %1, %2, %3;" : "=l"(d) : "l"(a), "l"(b), "l"(d)); }
__device__ __forceinline__ float2 unpack2(ull p) { float2 f; asm("mov.b64 {%0, %1}, %2;" : "=f"(f.x), "=f"(f.y) : "l"(p)); return f; }

// ---------------- CSR build ----------------
__global__ void k_init() {
    int i = blockIdx.x * blockDim.x + threadIdx.x;
    if (i < N_NODESC) g_deg[i] = 0;
    if (i < N_GRAPHSC * 3 * HC) g_pooled[i] = 0.f;
}
__global__ void k_hist(const int* __restrict__ ei) {
    int e = blockIdx.x * blockDim.x + threadIdx.x;
    if (e < N_EDGESC) atomicAdd(&g_deg[ei[N_EDGESC + e]], 1);
}
__global__ void k_scan() {
    __shared__ int wsum[32];
    __shared__ int ctot;
    int tid = threadIdx.x, lane = tid & 31, wid = tid >> 5;
    int carry = 0;
    for (int base = 0; base < N_NODESC; base += 4096) {
        int i = base + tid * 4;
        int4 v = make_int4(0, 0, 0, 0);
        if (i < N_NODESC) v = ((const int4*)g_deg)[base / 4 + tid];
        int s0 = v.x, s1 = s0 + v.y, s2 = s1 + v.z, s3 = s2 + v.w;
        int incl = s3;
        #pragma unroll
        for (int o = 1; o < 32; o <<= 1) { int t = __shfl_up_sync(~0u, incl, o); if (lane >= o) incl += t; }
        if (lane == 31) wsum[wid] = incl;
        __syncthreads();
        if (wid == 0) {
            int s = wsum[lane], si = s;
            #pragma unroll
            for (int o = 1; o < 32; o <<= 1) { int t = __shfl_up_sync(~0u, si, o); if (lane >= o) si += t; }
            wsum[lane] = si - s;
            if (lane == 31) ctot = si;
        }
        __syncthreads();
        int excl = carry + wsum[wid] + incl - s3;
        if (i < N_NODESC) {
            g_off[i] = excl;          g_pos[i] = excl;
            g_off[i + 1] = excl + s0; g_pos[i + 1] = excl + s0;
            g_off[i + 2] = excl + s1; g_pos[i + 2] = excl + s1;
            g_off[i + 3] = excl + s2; g_pos[i + 3] = excl + s2;
        }
        carry += ctot;
        __syncthreads();
    }
    if (tid == 0) g_off[N_NODESC] = carry;
}
__global__ void k_fill(const int* __restrict__ ei) {
    int e = blockIdx.x * blockDim.x + threadIdx.x;
    if (e < N_EDGESC) {
        int s = ei[e], d = ei[N_EDGESC + e];
        g_srcs[atomicAdd(&g_pos[d], 1)] = s;
    }
}
// pack weights into per-fragment order, hi/lo split. grid (16,5) x 256
__global__ void k_prep(const float* __restrict__ w0, const float* __restrict__ w1,
                       const float* __restrict__ w2, const float* __restrict__ w3,
                       const float* __restrict__ w4) {
    int m = blockIdx.y;
    const float* W = (m == 0) ? w0 : (m == 1) ? w1 : (m == 2) ? w2 : (m == 3) ? w3 : w4;
    int e = blockIdx.x * 256 + threadIdx.x;    // 0..4095
    int ks = e >> 9, nt = (e >> 5) & 15, l = e & 31;
    int k0 = ks * 16 + (l & 3) * 2;
    int n  = nt * 8 + (l >> 2);
    float v00 = W[k0 * 128 + n],       v01 = W[(k0 + 1) * 128 + n];
    float v10 = W[(k0 + 8) * 128 + n], v11 = W[(k0 + 9) * 128 + n];
    unsigned short h00, l00, h01, l01, h10, l10, h11, l11;
    bsplit(v00, h00, l00); bsplit(v01, h01, l01);
    bsplit(v10, h10, l10); bsplit(v11, h11, l11);
    g_wpack[2 * m][e]     = make_uint2((uint32_t)h00 | ((uint32_t)h01 << 16),
                                       (uint32_t)h10 | ((uint32_t)h11 << 16));
    g_wpack[2 * m + 1][e] = make_uint2((uint32_t)l00 | ((uint32_t)l01 << 16),
                                       (uint32_t)l10 | ((uint32_t)l11 << 16));
}

// ---------------- shared device pieces ----------------
__device__ __forceinline__ void stage_pack(uint4* Bs4, const uint2* __restrict__ src, int tid) {
    const uint4* s4 = (const uint4*)src;   // 2048 uint4
    #pragma unroll
    for (int j = 0; j < 4; j++) Bs4[tid + j * 512] = s4[tid + j * 512];
}
// one term pass: acc += A(16 rows at rb*16) x B (8 ntiles at cb*64)
__device__ __forceinline__ void mma_pass(const unsigned short* __restrict__ Asrc,
                                         const uint2* __restrict__ Bs,
                                         float acc[8][4], int rb, int cb, int g, int tc) {
    int row = rb * 16 + g;
    #pragma unroll
    for (int ks = 0; ks < 8; ks++) {
        int k0 = ks * 16 + tc;
        uint32_t a0 = *(const uint32_t*)&Asrc[row * AS + k0];
        uint32_t a1 = *(const uint32_t*)&Asrc[(row + 8) * AS + k0];
        uint32_t a2 = *(const uint32_t*)&Asrc[row * AS + k0 + 8];
        uint32_t a3 = *(const uint32_t*)&Asrc[(row + 8) * AS + k0 + 8];
        #pragma unroll
        for (int nt = 0; nt < 8; nt++) {
            uint2 b = Bs[(ks * 16 + cb * 8 + nt) * 32 + (g * 4 + (tc >> 1))];
            mma_bf16(acc[nt], a0, a1, a2, a3, b.x, b.y);
        }
    }
}
__device__ __forceinline__ void pool_tile(const float* __restrict__ T, const int* __restrict__ batchS, int seg, int tid) {
    int col = tid & 127, h0 = (tid >> 7) * 32;
    float acc = 0.f; int cur = -1;
    for (int rr = h0; rr < h0 + 32; rr++) {
        int g = batchS[rr];
        if (g < 0) break;
        if (g != cur) { if (cur >= 0) atomicAdd(&g_pooled[cur * 384 + seg * HC + col], acc); acc = 0.f; cur = g; }
        acc += T[rr * PSTRIDE + col];
    }
    if (cur >= 0) atomicAdd(&g_pooled[cur * 384 + seg * HC + col], acc);
}

// GEMM (3-term bf16) from split A tiles into acc; stages Blo in the middle
__device__ __forceinline__ void gemm3(const unsigned short* Ahi, const unsigned short* Alo,
                                      uint2* Bs, const uint2* __restrict__ whi,
                                      const uint2* __restrict__ wlo,
                                      float acc[8][4], int rb, int cb, int g, int tc, int tid) {
    // Bs holds whi (staged by caller, synced)
    mma_pass(Ahi, Bs, acc, rb, cb, g, tc);
    mma_pass(Alo, Bs, acc, rb, cb, g, tc);
    __syncthreads();
    stage_pack((uint4*)Bs, wlo, tid);
    __syncthreads();
    mma_pass(Ahi, Bs, acc, rb, cb, g, tc);
    __syncthreads();   // all A reads done before epilogue overwrites A
}

// ---------------- fused GIN layer (2,3) ----------------
__global__ __launch_bounds__(512, 2)
void k_layer(const float* __restrict__ hin,
             const uint2* __restrict__ w1hi, const uint2* __restrict__ w1lo, const float* __restrict__ b1v,
             const uint2* __restrict__ w2hi, const uint2* __restrict__ w2lo, const float* __restrict__ b2v,
             float* __restrict__ hout, const int* __restrict__ batch, int seg, int write_out) {
    extern __shared__ char dyn[];
    unsigned short* Ahi = (unsigned short*)dyn;                    // 128*136*2 = 34816 B
    unsigned short* Alo = (unsigned short*)(dyn + 34816);          // 34816 B
    uint2* Bs = (uint2*)(dyn + 69632);                             // 32768 B
    float* Pool = (float*)dyn;                                     // reuse A region
    __shared__ int batchS[128];

    int tid = threadIdx.x, lane = tid & 31, wid = tid >> 5;
    int rb = wid >> 1, cb = wid & 1;
    int g = lane >> 2, tc = (lane & 3) * 2;
    int row0 = blockIdx.x * 128;

    if (tid < 128) { int r = row0 + tid; batchS[tid] = (r < N_NODESC) ? batch[r] : -1; }
    stage_pack((uint4*)Bs, w1hi, tid);

    // aggregation -> split bf16 tiles
    const float4* xi = (const float4*)hin;
    #pragma unroll 1
    for (int t = 0; t < 8; t++) {
        int rr = wid + t * 16, row = row0 + rr;
        float4 acc = make_float4(0.f, 0.f, 0.f, 0.f);
        if (row < N_NODESC) {
            acc = xi[row * 32 + lane];
            float4 acc2 = make_float4(0.f, 0.f, 0.f, 0.f);
            int s0 = g_off[row], s1 = g_off[row + 1], j = s0;
            for (; j + 1 < s1; j += 2) {
                float4 vA = xi[g_srcs[j] * 32 + lane];
                float4 vB = xi[g_srcs[j + 1] * 32 + lane];
                acc.x += vA.x; acc.y += vA.y; acc.z += vA.z; acc.w += vA.w;
                acc2.x += vB.x; acc2.y += vB.y; acc2.z += vB.z; acc2.w += vB.w;
            }
            if (j < s1) {
                float4 v = xi[g_srcs[j] * 32 + lane];
                acc.x += v.x; acc.y += v.y; acc.z += v.z; acc.w += v.w;
            }
            acc.x += acc2.x; acc.y += acc2.y; acc.z += acc2.z; acc.w += acc2.w;
        }
        unsigned short h0, l0, h1, l1, h2, l2, h3, l3;
        bsplit(acc.x, h0, l0); bsplit(acc.y, h1, l1);
        bsplit(acc.z, h2, l2); bsplit(acc.w, h3, l3);
        int c = lane * 4;
        *(uint2*)&Ahi[rr * AS + c] = make_uint2((uint32_t)h0 | ((uint32_t)h1 << 16),
                                                (uint32_t)h2 | ((uint32_t)h3 << 16));
        *(uint2*)&Alo[rr * AS + c] = make_uint2((uint32_t)l0 | ((uint32_t)l1 << 16),
                                                (uint32_t)l2 | ((uint32_t)l3 << 16));
    }
    __syncthreads();

    float acc[8][4];
    #pragma unroll
    for (int i = 0; i < 8; i++) { acc[i][0] = acc[i][1] = acc[i][2] = acc[i][3] = 0.f; }
    gemm3(Ahi, Alo, Bs, w1hi, w1lo, acc, rb, cb, g, tc, tid);

    // epilogue1: relu(+b1) -> re-split into Ahi/Alo ; stage w2hi
    {
        int r0 = rb * 16 + g, r1 = r0 + 8;
        #pragma unroll
        for (int nt = 0; nt < 8; nt++) {
            int col = cb * 64 + nt * 8 + tc;
            float b0 = b1v[col], b1 = b1v[col + 1];
            float v0 = fmaxf(acc[nt][0] + b0, 0.f), v1 = fmaxf(acc[nt][1] + b1, 0.f);
            float v2 = fmaxf(acc[nt][2] + b0, 0.f), v3 = fmaxf(acc[nt][3] + b1, 0.f);
            unsigned short h0, l0, h1, l1, h2, l2, h3, l3;
            bsplit(v0, h0, l0); bsplit(v1, h1, l1); bsplit(v2, h2, l2); bsplit(v3, h3, l3);
            *(uint32_t*)&Ahi[r0 * AS + col] = (uint32_t)h0 | ((uint32_t)h1 << 16);
            *(uint32_t*)&Alo[r0 * AS + col] = (uint32_t)l0 | ((uint32_t)l1 << 16);
            *(uint32_t*)&Ahi[r1 * AS + col] = (uint32_t)h2 | ((uint32_t)h3 << 16);
            *(uint32_t*)&Alo[r1 * AS + col] = (uint32_t)l2 | ((uint32_t)l3 << 16);
        }
    }
    stage_pack((uint4*)Bs, w2hi, tid);
    __syncthreads();

    #pragma unroll
    for (int i = 0; i < 8; i++) { acc[i][0] = acc[i][1] = acc[i][2] = acc[i][3] = 0.f; }
    gemm3(Ahi, Alo, Bs, w2hi, w2lo, acc, rb, cb, g, tc, tid);

    // epilogue2: relu(+b2) -> pool tile (fp32, reuses A region)
    {
        int r0 = rb * 16 + g, r1 = r0 + 8;
        #pragma unroll
        for (int nt = 0; nt < 8; nt++) {
            int col = cb * 64 + nt * 8 + tc;
            float b0 = b2v[col], b1 = b2v[col + 1];
            *(float2*)&Pool[r0 * PSTRIDE + col] = make_float2(fmaxf(acc[nt][0] + b0, 0.f),
                                                              fmaxf(acc[nt][1] + b1, 0.f));
            *(float2*)&Pool[r1 * PSTRIDE + col] = make_float2(fmaxf(acc[nt][2] + b0, 0.f),
                                                              fmaxf(acc[nt][3] + b1, 0.f));
        }
    }
    __syncthreads();

    if (write_out) {
        #pragma unroll
        for (int j = 0; j < 8; j++) {
            int idx = tid + j * 512, r = idx >> 5, c4 = (idx & 31) * 4;
            if (row0 + r < N_NODESC)
                *(float4*)&hout[(row0 + r) * HC + c4] = *(const float4*)&Pool[r * PSTRIDE + c4];
        }
    }
    pool_tile(Pool, batchS, seg, tid);
}

// ---------------- fused layer 1 ----------------
__global__ __launch_bounds__(512, 2)
void k_layer1(const float* __restrict__ x, const float* __restrict__ W1, const float* __restrict__ b1v,
              const uint2* __restrict__ w2hi, const uint2* __restrict__ w2lo, const float* __restrict__ b2v,
              float* __restrict__ hout, const int* __restrict__ batch) {
    extern __shared__ char dyn[];
    unsigned short* Ahi = (unsigned short*)dyn;
    unsigned short* Alo = (unsigned short*)(dyn + 34816);
    uint2* Bs = (uint2*)(dyn + 69632);
    float* A8 = (float*)(dyn + 69632 + 32768);        // 128x8 fp32 = 4096
    float* B8 = (float*)(dyn + 69632 + 32768 + 4096); // 8x128 fp32 = 4096
    float* Pool = (float*)dyn;
    __shared__ int batchS[128];

    int tid = threadIdx.x, lane = tid & 31, wid = tid >> 5;
    int rb = wid >> 1, cb = wid & 1;
    int g = lane >> 2, tc = (lane & 3) * 2;
    int row0 = blockIdx.x * 128;

    if (tid < 128) { int r = row0 + tid; batchS[tid] = (r < N_NODESC) ? batch[r] : -1; }
    if (tid < 256) ((float4*)B8)[tid] = ((const float4*)W1)[tid];
    stage_pack((uint4*)Bs, w2hi, tid);

    // agg8 (256 threads, 2/row)
    if (tid < 256) {
        int row_l = tid >> 1, half = tid & 1, row = row0 + row_l;
        float4 a = make_float4(0.f, 0.f, 0.f, 0.f);
        if (row < N_NODESC) {
            const float4* x4 = (const float4*)x;
            a = x4[row * 2 + half];
            int s0 = g_off[row], s1 = g_off[row + 1];
            for (int j = s0; j < s1; j++) {
                float4 v = x4[g_srcs[j] * 2 + half];
                a.x += v.x; a.y += v.y; a.z += v.z; a.w += v.w;
            }
        }
        *(float4*)&A8[row_l * 8 + half * 4] = a;
    }
    __syncthreads();

    // GEMM1 K=8 (FFMA2, 256 threads) -> split bf16 tiles
    if (tid < 256) {
        int tx = tid & 15, ty = tid >> 4, r0 = ty * 8, c0 = tx * 4;
        ull fac[8][4];
        #pragma unroll
        for (int i = 0; i < 8; i++) { fac[i][0] = fac[i][1] = fac[i][2] = fac[i][3] = 0ull; }
        #pragma unroll
        for (int k = 0; k < 8; k++) {
            float a[8];
            #pragma unroll
            for (int i = 0; i < 8; i++) a[i] = A8[(r0 + i) * 8 + k];
            float4 bl = *(const float4*)&B8[k * 128 + c0];
            float4 bh = *(const float4*)&B8[k * 128 + c0 + 64];
            ull b0 = pack2(bl.x, bl.y), b1p = pack2(bl.z, bl.w);
            ull b2p = pack2(bh.x, bh.y), b3p = pack2(bh.z, bh.w);
            #pragma unroll
            for (int i = 0; i < 8; i++) {
                ull aa = pack2(a[i], a[i]);
                ffma2(fac[i][0], aa, b0); ffma2(fac[i][1], aa, b1p);
                ffma2(fac[i][2], aa, b2p); ffma2(fac[i][3], aa, b3p);
            }
        }
        float4 bll = *(const float4*)&b1v[c0];
        float4 blh = *(const float4*)&b1v[c0 + 64];
        #pragma unroll
        for (int i = 0; i < 8; i++) {
            float2 p0 = unpack2(fac[i][0]), p1 = unpack2(fac[i][1]);
            float2 p2 = unpack2(fac[i][2]), p3 = unpack2(fac[i][3]);
            float v[8] = { fmaxf(p0.x + bll.x, 0.f), fmaxf(p0.y + bll.y, 0.f),
                           fmaxf(p1.x + bll.z, 0.f), fmaxf(p1.y + bll.w, 0.f),
                           fmaxf(p2.x + blh.x, 0.f), fmaxf(p2.y + blh.y, 0.f),
                           fmaxf(p3.x + blh.z, 0.f), fmaxf(p3.y + blh.w, 0.f) };
            #pragma unroll
            for (int q = 0; q < 8; q++) {
                unsigned short hh, ll;
                bsplit(v[q], hh, ll);
                int col = (q < 4) ? (c0 + q) : (c0 + 64 + q - 4);
                Ahi[(r0 + i) * AS + col] = hh;
                Alo[(r0 + i) * AS + col] = ll;
            }
        }
    }
    __syncthreads();

    float acc[8][4];
    #pragma unroll
    for (int i = 0; i < 8; i++) { acc[i][0] = acc[i][1] = acc[i][2] = acc[i][3] = 0.f; }
    gemm3(Ahi, Alo, Bs, w2hi, w2lo, acc, rb, cb, g, tc, tid);

    {
        int r0 = rb * 16 + g, r1 = r0 + 8;
        #pragma unroll
        for (int nt = 0; nt < 8; nt++) {
            int col = cb * 64 + nt * 8 + tc;
            float b0 = b2v[col], b1 = b2v[col + 1];
            *(float2*)&Pool[r0 * PSTRIDE + col] = make_float2(fmaxf(acc[nt][0] + b0, 0.f),
                                                              fmaxf(acc[nt][1] + b1, 0.f));
            *(float2*)&Pool[r1 * PSTRIDE + col] = make_float2(fmaxf(acc[nt][2] + b0, 0.f),
                                                              fmaxf(acc[nt][3] + b1, 0.f));
        }
    }
    __syncthreads();
    #pragma unroll
    for (int j = 0; j < 8; j++) {
        int idx = tid + j * 512, r = idx >> 5, c4 = (idx & 31) * 4;
        if (row0 + r < N_NODESC)
            *(float4*)&hout[(row0 + r) * HC + c4] = *(const float4*)&Pool[r * PSTRIDE + c4];
    }
    pool_tile(Pool, batchS, 0, tid);
}

// ---------------- classifier ----------------
__global__ void k_cls(const float* __restrict__ W1, const float* __restrict__ b1,
                      const float* __restrict__ bng, const float* __restrict__ bnb,
                      const float* __restrict__ bnm, const float* __restrict__ bnv,
                      const float* __restrict__ W2, const float* __restrict__ b2,
                      float* __restrict__ out) {
    __shared__ float ps[384];
    __shared__ float zs[256];
    int gph = blockIdx.x, tid = threadIdx.x;
    for (int i = tid; i < 384; i += 256) ps[i] = g_pooled[gph * 384 + i];
    __syncthreads();
    float acc = b1[tid];
    for (int k = 0; k < 384; k++) acc += ps[k] * W1[k * 256 + tid];
    acc = (acc - bnm[tid]) * rsqrtf(bnv[tid] + 1e-5f) * bng[tid] + bnb[tid];
    zs[tid] = fmaxf(acc, 0.f);
    __syncthreads();
    if (tid < 4) {
        float s = b2[tid];
        for (int k = 0; k < 256; k++) s += zs[k] * W2[k * 4 + tid];
        out[gph * 4 + tid] = s;
    }
}

// ---------------- launch ----------------
extern "C" void kernel_launch(void* const* d_in, const int* in_sizes, int n_in,
                              void* d_out, int out_size) {
    const float* x   = (const float*)d_in[0];
    const int* ei    = (const int*)d_in[1];
    const int* batch = (const int*)d_in[2];
    const float* l1W1 = (const float*)d_in[3];
    const float* l1b1 = (const float*)d_in[4];
    const float* l1W2 = (const float*)d_in[5];
    const float* l1b2 = (const float*)d_in[6];
    const float* l2W1 = (const float*)d_in[7];
    const float* l2b1 = (const float*)d_in[8];
    const float* l2W2 = (const float*)d_in[9];
    const float* l2b2 = (const float*)d_in[10];
    const float* l3W1 = (const float*)d_in[11];
    const float* l3b1 = (const float*)d_in[12];
    const float* l3W2 = (const float*)d_in[13];
    const float* l3b2 = (const float*)d_in[14];
    const float* cW1  = (const float*)d_in[15];
    const float* cb1  = (const float*)d_in[16];
    const float* bng  = (const float*)d_in[17];
    const float* bnb  = (const float*)d_in[18];
    const float* bnm  = (const float*)d_in[19];
    const float* bnv  = (const float*)d_in[20];
    const float* cW2  = (const float*)d_in[21];
    const float* cb2  = (const float*)d_in[22];
    float* out = (float*)d_out;

    float *h1, *h2;
    uint2* wp;
    cudaGetSymbolAddress((void**)&h1, g_h1);
    cudaGetSymbolAddress((void**)&h2, g_h2);
    cudaGetSymbolAddress((void**)&wp, g_wpack);

    const int LAYER_SMEM  = 34816 * 2 + 32768;             // 102400
    const int LAYER1_SMEM = LAYER_SMEM + 4096 + 4096;      // 110592
    cudaFuncSetAttribute(k_layer,  cudaFuncAttributeMaxDynamicSharedMemorySize, LAYER_SMEM);
    cudaFuncSetAttribute(k_layer1, cudaFuncAttributeMaxDynamicSharedMemorySize, LAYER1_SMEM);

    const int blocks = (N_NODESC + 127) / 128;   // 391

    k_init<<<(N_NODESC + 255) / 256, 256>>>();
    k_hist<<<(N_EDGESC + 255) / 256, 256>>>(ei);
    k_scan<<<1, 1024>>>();
    k_fill<<<(N_EDGESC + 255) / 256, 256>>>(ei);
    k_prep<<<dim3(16, 5), 256>>>(l1W2, l2W1, l2W2, l3W1, l3W2);

    k_layer1<<<blocks, 512, LAYER1_SMEM>>>(x, l1W1, l1b1, wp, wp + 4096, l1b2, h1, batch);
    k_layer<<<blocks, 512, LAYER_SMEM>>>(h1, wp + 2 * 4096, wp + 3 * 4096, l2b1,
                                         wp + 4 * 4096, wp + 5 * 4096, l2b2, h2, batch, 1, 1);
    k_layer<<<blocks, 512, LAYER_SMEM>>>(h2, wp + 6 * 4096, wp + 7 * 4096, l3b1,
                                         wp + 8 * 4096, wp + 9 * 4096, l3b2, h2, batch, 2, 0);
    k_cls<<<N_GRAPHSC, 256>>>(cW1, cb1, bng, bnb, bnm, bnv, cW2, cb2, out);
}

// round 9
// speedup vs baseline: 1.2137x; 1.2137x over previous
#include <cuda_runtime.h>
#include <math.h>
#include <stdint.h>

#define N_NODESC 50000
#define N_EDGESC 640000
#define N_GRAPHSC 64
#define HC 128
#define TILE 64
#define AST 132
typedef unsigned long long ull;

__device__ __align__(16) int   g_deg[N_NODESC];
__device__ __align__(16) int   g_off[N_NODESC + 1];
__device__ __align__(16) int   g_pos[N_NODESC];
__device__ __align__(16) int   g_srcs[N_EDGESC];
__device__ __align__(16) float g_h1[N_NODESC * HC];
__device__ __align__(16) float g_h2[N_NODESC * HC];
__device__ __align__(16) float g_pooled[N_GRAPHSC * 3 * HC];

__device__ __forceinline__ ull pack2(float x, float y) { ull r; asm("mov.b64 %0, {%1, %2};" : "=l"(r) : "f"(x), "f"(y)); return r; }
__device__ __forceinline__ void ffma2(ull& d, ull a, ull b) { asm("fma.rn.f32x2 %0, %1, %2, %3;" : "=l"(d) : "l"(a), "l"(b), "l"(d)); }
__device__ __forceinline__ float2 unpack2(ull p) { float2 f; asm("mov.b64 {%0, %1}, %2;" : "=f"(f.x), "=f"(f.y) : "l"(p)); return f; }

// ---------------- CSR build ----------------
__global__ void k_init() {
    int i = blockIdx.x * blockDim.x + threadIdx.x;
    if (i < N_NODESC) g_deg[i] = 0;
    if (i < N_GRAPHSC * 3 * HC) g_pooled[i] = 0.f;
}
__global__ void k_hist(const int* __restrict__ ei) {
    int e = blockIdx.x * blockDim.x + threadIdx.x;
    if (e < N_EDGESC) atomicAdd(&g_deg[ei[N_EDGESC + e]], 1);
}
__global__ void k_scan() {
    __shared__ int wsum[32];
    __shared__ int ctot;
    int tid = threadIdx.x, lane = tid & 31, wid = tid >> 5;
    int carry = 0;
    for (int base = 0; base < N_NODESC; base += 4096) {
        int i = base + tid * 4;
        int4 v = make_int4(0, 0, 0, 0);
        if (i < N_NODESC) v = ((const int4*)g_deg)[base / 4 + tid];
        int s0 = v.x, s1 = s0 + v.y, s2 = s1 + v.z, s3 = s2 + v.w;
        int incl = s3;
        #pragma unroll
        for (int o = 1; o < 32; o <<= 1) { int t = __shfl_up_sync(~0u, incl, o); if (lane >= o) incl += t; }
        if (lane == 31) wsum[wid] = incl;
        __syncthreads();
        if (wid == 0) {
            int s = wsum[lane], si = s;
            #pragma unroll
            for (int o = 1; o < 32; o <<= 1) { int t = __shfl_up_sync(~0u, si, o); if (lane >= o) si += t; }
            wsum[lane] = si - s;
            if (lane == 31) ctot = si;
        }
        __syncthreads();
        int excl = carry + wsum[wid] + incl - s3;
        if (i < N_NODESC) {
            g_off[i] = excl;          g_pos[i] = excl;
            g_off[i + 1] = excl + s0; g_pos[i + 1] = excl + s0;
            g_off[i + 2] = excl + s1; g_pos[i + 2] = excl + s1;
            g_off[i + 3] = excl + s2; g_pos[i + 3] = excl + s2;
        }
        carry += ctot;
        __syncthreads();
    }
    if (tid == 0) g_off[N_NODESC] = carry;
}
__global__ void k_fill(const int* __restrict__ ei) {
    int e = blockIdx.x * blockDim.x + threadIdx.x;
    if (e < N_EDGESC) {
        int s = ei[e], d = ei[N_EDGESC + e];
        g_srcs[atomicAdd(&g_pos[d], 1)] = s;
    }
}

// ---------------- shared device pieces ----------------
// 64x128 GEMM phase: 256 threads, micro 4 rows x (4+4 split) cols, FFMA2.
__device__ __forceinline__ void gemm_tile(const float* __restrict__ At, int astride,
                                          const float* __restrict__ Bs, int K,
                                          ull acc[4][4], int r0, int c0) {
    #pragma unroll 4
    for (int k = 0; k < K; k++) {
        float a[4];
        #pragma unroll
        for (int i = 0; i < 4; i++) a[i] = At[(r0 + i) * astride + k];
        float4 bl = *(const float4*)&Bs[k * 128 + c0];
        float4 bh = *(const float4*)&Bs[k * 128 + c0 + 64];
        ull b0 = pack2(bl.x, bl.y), b1p = pack2(bl.z, bl.w);
        ull b2p = pack2(bh.x, bh.y), b3p = pack2(bh.z, bh.w);
        #pragma unroll
        for (int i = 0; i < 4; i++) {
            ull aa = pack2(a[i], a[i]);
            ffma2(acc[i][0], aa, b0); ffma2(acc[i][1], aa, b1p);
            ffma2(acc[i][2], aa, b2p); ffma2(acc[i][3], aa, b3p);
        }
    }
}
__device__ __forceinline__ void epi_relu(const ull acc[4], const float* __restrict__ bias,
                                         int c0, float4& lo, float4& hi) {
    float4 bl = *(const float4*)&bias[c0];
    float4 bh = *(const float4*)&bias[c0 + 64];
    float2 p0 = unpack2(acc[0]), p1 = unpack2(acc[1]);
    float2 p2 = unpack2(acc[2]), p3 = unpack2(acc[3]);
    lo = make_float4(fmaxf(p0.x + bl.x, 0.f), fmaxf(p0.y + bl.y, 0.f),
                     fmaxf(p1.x + bl.z, 0.f), fmaxf(p1.y + bl.w, 0.f));
    hi = make_float4(fmaxf(p2.x + bh.x, 0.f), fmaxf(p2.y + bh.y, 0.f),
                     fmaxf(p3.x + bh.z, 0.f), fmaxf(p3.y + bh.w, 0.f));
}
// pool 64-row tile (stride AST), 256 threads: col tid&127, 2 groups x 32 rows
__device__ __forceinline__ void pool_tile(const float* __restrict__ T,
                                          const int* __restrict__ batchS, int seg, int tid) {
    int col = tid & 127, h0 = (tid >> 7) * 32;
    float acc = 0.f; int cur = -1;
    for (int rr = h0; rr < h0 + 32; rr++) {
        int g = batchS[rr];
        if (g < 0) break;
        if (g != cur) { if (cur >= 0) atomicAdd(&g_pooled[cur * 384 + seg * HC + col], acc); acc = 0.f; cur = g; }
        acc += T[rr * AST + col];
    }
    if (cur >= 0) atomicAdd(&g_pooled[cur * 384 + seg * HC + col], acc);
}
__device__ __forceinline__ void addf4(float4& a, float4 v) {
    a.x += v.x; a.y += v.y; a.z += v.z; a.w += v.w;
}

// ---------------- fused GIN layer (2,3): agg + MLP + pool, occ2 ----------------
__global__ __launch_bounds__(256, 2)
void k_layer(const float* __restrict__ hin,
             const float* __restrict__ W1, const float* __restrict__ b1v,
             const float* __restrict__ W2, const float* __restrict__ b2v,
             float* __restrict__ hout, const int* __restrict__ batch,
             int seg, int write_out) {
    extern __shared__ float sm[];
    float* As = sm;                 // TILE x AST (agg -> mid -> h/pool)
    float* Bs = sm + TILE * AST;    // 128 x 128 single weight buffer
    __shared__ int batchS[TILE];

    int tid = threadIdx.x, lane = tid & 31, wid = tid >> 5;
    int row0 = blockIdx.x * TILE;

    // stage W1 (overlaps with agg loads below)
    #pragma unroll
    for (int t = 0; t < 16; t++)
        ((float4*)Bs)[tid + t * 256] = ((const float4*)W1)[tid + t * 256];
    if (tid < TILE) { int r = row0 + tid; batchS[tid] = (r < N_NODESC) ? batch[r] : -1; }

    // aggregation: 8 warps x 8 rows, MLP-4 unroll
    const float4* xi = (const float4*)hin;
    for (int rr = wid; rr < TILE; rr += 8) {
        int row = row0 + rr;
        float4 a0 = make_float4(0.f, 0.f, 0.f, 0.f);
        float4 a1 = a0, a2 = a0, a3 = a0;
        if (row < N_NODESC) {
            a0 = xi[row * 32 + lane];
            int s0 = g_off[row], s1 = g_off[row + 1], j = s0;
            for (; j + 3 < s1; j += 4) {
                addf4(a0, xi[g_srcs[j] * 32 + lane]);
                addf4(a1, xi[g_srcs[j + 1] * 32 + lane]);
                addf4(a2, xi[g_srcs[j + 2] * 32 + lane]);
                addf4(a3, xi[g_srcs[j + 3] * 32 + lane]);
            }
            for (; j < s1; j++) addf4(a0, xi[g_srcs[j] * 32 + lane]);
        }
        addf4(a0, a1); addf4(a2, a3); addf4(a0, a2);
        *(float4*)&As[rr * AST + lane * 4] = a0;
    }
    __syncthreads();

    int tx = tid & 15, ty = tid >> 4;
    int r0 = ty * 4, c0 = tx * 4;

    // GEMM1: mid = relu(agg @ W1 + b1)
    ull acc[4][4];
    #pragma unroll
    for (int i = 0; i < 4; i++) { acc[i][0] = acc[i][1] = acc[i][2] = acc[i][3] = 0ull; }
    gemm_tile(As, AST, Bs, 128, acc, r0, c0);
    __syncthreads();     // reads of As(agg) and Bs(W1) done
    #pragma unroll
    for (int i = 0; i < 4; i++) {
        float4 lo, hi;
        epi_relu(acc[i], b1v, c0, lo, hi);
        *(float4*)&As[(r0 + i) * AST + c0] = lo;
        *(float4*)&As[(r0 + i) * AST + c0 + 64] = hi;
    }
    // restage W2
    #pragma unroll
    for (int t = 0; t < 16; t++)
        ((float4*)Bs)[tid + t * 256] = ((const float4*)W2)[tid + t * 256];
    __syncthreads();

    // GEMM2: h = relu(mid @ W2 + b2)
    #pragma unroll
    for (int i = 0; i < 4; i++) { acc[i][0] = acc[i][1] = acc[i][2] = acc[i][3] = 0ull; }
    gemm_tile(As, AST, Bs, 128, acc, r0, c0);
    __syncthreads();     // reads of As(mid) done
    #pragma unroll
    for (int i = 0; i < 4; i++) {
        float4 lo, hi;
        epi_relu(acc[i], b2v, c0, lo, hi);
        int rr = r0 + i, row = row0 + rr;
        *(float4*)&As[rr * AST + c0] = lo;
        *(float4*)&As[rr * AST + c0 + 64] = hi;
        if (write_out && row < N_NODESC) {
            *(float4*)&hout[row * HC + c0] = lo;
            *(float4*)&hout[row * HC + c0 + 64] = hi;
        }
    }
    __syncthreads();
    pool_tile(As, batchS, seg, tid);
}

// ---------------- fused layer 1: agg8 + MLP(8->128->128) + pool ----------------
__global__ __launch_bounds__(256, 2)
void k_layer1(const float* __restrict__ x,
              const float* __restrict__ W1, const float* __restrict__ b1v,
              const float* __restrict__ W2, const float* __restrict__ b2v,
              float* __restrict__ hout, const int* __restrict__ batch) {
    extern __shared__ float sm[];
    float* As = sm;                         // TILE x AST
    float* Bs = sm + TILE * AST;            // 128 x 128 (W2)
    float* A8 = Bs + 128 * 128;             // TILE x 8
    float* B8 = A8 + TILE * 8;              // 8 x 128 (W1)
    __shared__ int batchS[TILE];

    int tid = threadIdx.x;
    int row0 = blockIdx.x * TILE;

    ((float4*)B8)[tid] = ((const float4*)W1)[tid];   // 256 float4 = 1024 floats
    #pragma unroll
    for (int t = 0; t < 16; t++)
        ((float4*)Bs)[tid + t * 256] = ((const float4*)W2)[tid + t * 256];
    if (tid < TILE) { int r = row0 + tid; batchS[tid] = (r < N_NODESC) ? batch[r] : -1; }

    // agg8: 2 threads per row (first 128 threads)
    if (tid < 2 * TILE) {
        int row_l = tid >> 1, half = tid & 1, row = row0 + row_l;
        float4 a = make_float4(0.f, 0.f, 0.f, 0.f);
        if (row < N_NODESC) {
            const float4* x4 = (const float4*)x;
            a = x4[row * 2 + half];
            int s0 = g_off[row], s1 = g_off[row + 1];
            for (int j = s0; j < s1; j++) addf4(a, x4[g_srcs[j] * 2 + half]);
        }
        *(float4*)&A8[row_l * 8 + half * 4] = a;
    }
    __syncthreads();

    int tx = tid & 15, ty = tid >> 4;
    int r0 = ty * 4, c0 = tx * 4;

    // GEMM1 (K=8): mid = relu(agg8 @ W1 + b1) -> As
    ull acc[4][4];
    #pragma unroll
    for (int i = 0; i < 4; i++) { acc[i][0] = acc[i][1] = acc[i][2] = acc[i][3] = 0ull; }
    gemm_tile(A8, 8, B8, 8, acc, r0, c0);
    #pragma unroll
    for (int i = 0; i < 4; i++) {
        float4 lo, hi;
        epi_relu(acc[i], b1v, c0, lo, hi);
        *(float4*)&As[(r0 + i) * AST + c0] = lo;
        *(float4*)&As[(r0 + i) * AST + c0 + 64] = hi;
    }
    __syncthreads();

    // GEMM2: h1 = relu(mid @ W2 + b2)
    #pragma unroll
    for (int i = 0; i < 4; i++) { acc[i][0] = acc[i][1] = acc[i][2] = acc[i][3] = 0ull; }
    gemm_tile(As, AST, Bs, 128, acc, r0, c0);
    __syncthreads();
    #pragma unroll
    for (int i = 0; i < 4; i++) {
        float4 lo, hi;
        epi_relu(acc[i], b2v, c0, lo, hi);
        int rr = r0 + i, row = row0 + rr;
        *(float4*)&As[rr * AST + c0] = lo;
        *(float4*)&As[rr * AST + c0 + 64] = hi;
        if (row < N_NODESC) {
            *(float4*)&hout[row * HC + c0] = lo;
            *(float4*)&hout[row * HC + c0 + 64] = hi;
        }
    }
    __syncthreads();
    pool_tile(As, batchS, 0, tid);
}

// ---------------- classifier ----------------
__global__ void k_cls(const float* __restrict__ W1, const float* __restrict__ b1,
                      const float* __restrict__ bng, const float* __restrict__ bnb,
                      const float* __restrict__ bnm, const float* __restrict__ bnv,
                      const float* __restrict__ W2, const float* __restrict__ b2,
                      float* __restrict__ out) {
    __shared__ float ps[384];
    __shared__ float zs[256];
    int gph = blockIdx.x, tid = threadIdx.x;
    for (int i = tid; i < 384; i += 256) ps[i] = g_pooled[gph * 384 + i];
    __syncthreads();
    float acc = b1[tid];
    for (int k = 0; k < 384; k++) acc += ps[k] * W1[k * 256 + tid];
    acc = (acc - bnm[tid]) * rsqrtf(bnv[tid] + 1e-5f) * bng[tid] + bnb[tid];
    zs[tid] = fmaxf(acc, 0.f);
    __syncthreads();
    if (tid < 4) {
        float s = b2[tid];
        for (int k = 0; k < 256; k++) s += zs[k] * W2[k * 4 + tid];
        out[gph * 4 + tid] = s;
    }
}

// ---------------- launch ----------------
extern "C" void kernel_launch(void* const* d_in, const int* in_sizes, int n_in,
                              void* d_out, int out_size) {
    const float* x   = (const float*)d_in[0];
    const int* ei    = (const int*)d_in[1];
    const int* batch = (const int*)d_in[2];
    const float* l1W1 = (const float*)d_in[3];
    const float* l1b1 = (const float*)d_in[4];
    const float* l1W2 = (const float*)d_in[5];
    const float* l1b2 = (const float*)d_in[6];
    const float* l2W1 = (const float*)d_in[7];
    const float* l2b1 = (const float*)d_in[8];
    const float* l2W2 = (const float*)d_in[9];
    const float* l2b2 = (const float*)d_in[10];
    const float* l3W1 = (const float*)d_in[11];
    const float* l3b1 = (const float*)d_in[12];
    const float* l3W2 = (const float*)d_in[13];
    const float* l3b2 = (const float*)d_in[14];
    const float* cW1  = (const float*)d_in[15];
    const float* cb1  = (const float*)d_in[16];
    const float* bng  = (const float*)d_in[17];
    const float* bnb  = (const float*)d_in[18];
    const float* bnm  = (const float*)d_in[19];
    const float* bnv  = (const float*)d_in[20];
    const float* cW2  = (const float*)d_in[21];
    const float* cb2  = (const float*)d_in[22];
    float* out = (float*)d_out;

    float *h1, *h2;
    cudaGetSymbolAddress((void**)&h1, g_h1);
    cudaGetSymbolAddress((void**)&h2, g_h2);

    const int LAYER_SMEM  = (TILE * AST + 128 * 128) * 4;                       // 99328
    const int LAYER1_SMEM = LAYER_SMEM + (TILE * 8 + 8 * 128) * 4;              // 105472
    cudaFuncSetAttribute(k_layer,  cudaFuncAttributeMaxDynamicSharedMemorySize, LAYER_SMEM);
    cudaFuncSetAttribute(k_layer1, cudaFuncAttributeMaxDynamicSharedMemorySize, LAYER1_SMEM);

    const int blocks = (N_NODESC + TILE - 1) / TILE;   // 782

    k_init<<<(N_NODESC + 255) / 256, 256>>>();
    k_hist<<<(N_EDGESC + 255) / 256, 256>>>(ei);
    k_scan<<<1, 1024>>>();
    k_fill<<<(N_EDGESC + 255) / 256, 256>>>(ei);

    k_layer1<<<blocks, 256, LAYER1_SMEM>>>(x, l1W1, l1b1, l1W2, l1b2, h1, batch);
    k_layer<<<blocks, 256, LAYER_SMEM>>>(h1, l2W1, l2b1, l2W2, l2b2, h2, batch, 1, 1);
    k_layer<<<blocks, 256, LAYER_SMEM>>>(h2, l3W1, l3b1, l3W2, l3b2, h2, batch, 2, 0);

    k_cls<<<N_GRAPHSC, 256>>>(cW1, cb1, bng, bnb, bnm, bnv, cW2, cb2, out);
}

// round 10
// speedup vs baseline: 1.2370x; 1.0192x over previous
#include <cuda_runtime.h>
#include <math.h>
#include <stdint.h>

#define N_NODESC 50000
#define N_EDGESC 640000
#define N_GRAPHSC 64
#define HC 128
#define TILE 64
#define AST 132
typedef unsigned long long ull;

__device__ __align__(16) int   g_deg[N_NODESC];
__device__ __align__(16) int   g_off[N_NODESC + 1];
__device__ __align__(16) int   g_pos[N_NODESC];
__device__ __align__(16) int   g_srcs[N_EDGESC];
__device__ __align__(16) float g_h1[N_NODESC * HC];
__device__ __align__(16) float g_h2[N_NODESC * HC];
__device__ __align__(16) float g_pooled[N_GRAPHSC * 3 * HC];

__device__ __forceinline__ ull pack2(float x, float y) { ull r; asm("mov.b64 %0, {%1, %2};" : "=l"(r) : "f"(x), "f"(y)); return r; }
__device__ __forceinline__ void ffma2(ull& d, ull a, ull b) { asm("fma.rn.f32x2 %0, %1, %2, %3;" : "=l"(d) : "l"(a), "l"(b), "l"(d)); }
__device__ __forceinline__ float2 unpack2(ull p) { float2 f; asm("mov.b64 {%0, %1}, %2;" : "=f"(f.x), "=f"(f.y) : "l"(p)); return f; }

// ---------------- CSR build ----------------
__global__ void k_init() {
    int i = blockIdx.x * blockDim.x + threadIdx.x;
    if (i < N_NODESC) g_deg[i] = 0;
    if (i < N_GRAPHSC * 3 * HC) g_pooled[i] = 0.f;
}
// 4 edges/thread
__global__ void k_hist(const int* __restrict__ ei) {
    int e4 = blockIdx.x * blockDim.x + threadIdx.x;
    if (e4 < N_EDGESC / 4) {
        int4 d = ((const int4*)(ei + N_EDGESC))[e4];
        atomicAdd(&g_deg[d.x], 1);
        atomicAdd(&g_deg[d.y], 1);
        atomicAdd(&g_deg[d.z], 1);
        atomicAdd(&g_deg[d.w], 1);
    }
}
__global__ void k_scan() {
    __shared__ int wsum[32];
    __shared__ int ctot;
    int tid = threadIdx.x, lane = tid & 31, wid = tid >> 5;
    int carry = 0;
    for (int base = 0; base < N_NODESC; base += 4096) {
        int i = base + tid * 4;
        int4 v = make_int4(0, 0, 0, 0);
        if (i < N_NODESC) v = ((const int4*)g_deg)[base / 4 + tid];
        int s0 = v.x, s1 = s0 + v.y, s2 = s1 + v.z, s3 = s2 + v.w;
        int incl = s3;
        #pragma unroll
        for (int o = 1; o < 32; o <<= 1) { int t = __shfl_up_sync(~0u, incl, o); if (lane >= o) incl += t; }
        if (lane == 31) wsum[wid] = incl;
        __syncthreads();
        if (wid == 0) {
            int s = wsum[lane], si = s;
            #pragma unroll
            for (int o = 1; o < 32; o <<= 1) { int t = __shfl_up_sync(~0u, si, o); if (lane >= o) si += t; }
            wsum[lane] = si - s;
            if (lane == 31) ctot = si;
        }
        __syncthreads();
        int excl = carry + wsum[wid] + incl - s3;
        if (i < N_NODESC) {
            g_off[i] = excl;          g_pos[i] = excl;
            g_off[i + 1] = excl + s0; g_pos[i + 1] = excl + s0;
            g_off[i + 2] = excl + s1; g_pos[i + 2] = excl + s1;
            g_off[i + 3] = excl + s2; g_pos[i + 3] = excl + s2;
        }
        carry += ctot;
        __syncthreads();
    }
    if (tid == 0) g_off[N_NODESC] = carry;
}
// 4 edges/thread
__global__ void k_fill(const int* __restrict__ ei) {
    int e4 = blockIdx.x * blockDim.x + threadIdx.x;
    if (e4 < N_EDGESC / 4) {
        int4 s = ((const int4*)ei)[e4];
        int4 d = ((const int4*)(ei + N_EDGESC))[e4];
        g_srcs[atomicAdd(&g_pos[d.x], 1)] = s.x;
        g_srcs[atomicAdd(&g_pos[d.y], 1)] = s.y;
        g_srcs[atomicAdd(&g_pos[d.z], 1)] = s.z;
        g_srcs[atomicAdd(&g_pos[d.w], 1)] = s.w;
    }
}

// ---------------- shared device pieces ----------------
__device__ __forceinline__ void gemm_tile(const float* __restrict__ At, int astride,
                                          const float* __restrict__ Bs, int K,
                                          ull acc[4][4], int r0, int c0) {
    #pragma unroll 4
    for (int k = 0; k < K; k++) {
        float a[4];
        #pragma unroll
        for (int i = 0; i < 4; i++) a[i] = At[(r0 + i) * astride + k];
        float4 bl = *(const float4*)&Bs[k * 128 + c0];
        float4 bh = *(const float4*)&Bs[k * 128 + c0 + 64];
        ull b0 = pack2(bl.x, bl.y), b1p = pack2(bl.z, bl.w);
        ull b2p = pack2(bh.x, bh.y), b3p = pack2(bh.z, bh.w);
        #pragma unroll
        for (int i = 0; i < 4; i++) {
            ull aa = pack2(a[i], a[i]);
            ffma2(acc[i][0], aa, b0); ffma2(acc[i][1], aa, b1p);
            ffma2(acc[i][2], aa, b2p); ffma2(acc[i][3], aa, b3p);
        }
    }
}
__device__ __forceinline__ void epi_relu(const ull acc[4], const float* __restrict__ bias,
                                         int c0, float4& lo, float4& hi) {
    float4 bl = *(const float4*)&bias[c0];
    float4 bh = *(const float4*)&bias[c0 + 64];
    float2 p0 = unpack2(acc[0]), p1 = unpack2(acc[1]);
    float2 p2 = unpack2(acc[2]), p3 = unpack2(acc[3]);
    lo = make_float4(fmaxf(p0.x + bl.x, 0.f), fmaxf(p0.y + bl.y, 0.f),
                     fmaxf(p1.x + bl.z, 0.f), fmaxf(p1.y + bl.w, 0.f));
    hi = make_float4(fmaxf(p2.x + bh.x, 0.f), fmaxf(p2.y + bh.y, 0.f),
                     fmaxf(p3.x + bh.z, 0.f), fmaxf(p3.y + bh.w, 0.f));
}
__device__ __forceinline__ void pool_tile(const float* __restrict__ T,
                                          const int* __restrict__ batchS, int seg, int tid) {
    int col = tid & 127, h0 = (tid >> 7) * 32;
    float acc = 0.f; int cur = -1;
    for (int rr = h0; rr < h0 + 32; rr++) {
        int g = batchS[rr];
        if (g < 0) break;
        if (g != cur) { if (cur >= 0) atomicAdd(&g_pooled[cur * 384 + seg * HC + col], acc); acc = 0.f; cur = g; }
        acc += T[rr * AST + col];
    }
    if (cur >= 0) atomicAdd(&g_pooled[cur * 384 + seg * HC + col], acc);
}
__device__ __forceinline__ void addf4(float4& a, float4 v) {
    a.x += v.x; a.y += v.y; a.z += v.z; a.w += v.w;
}

// ---------------- fused GIN layer (2,3): agg + MLP + pool, occ2 ----------------
__global__ __launch_bounds__(256, 2)
void k_layer(const float* __restrict__ hin,
             const float* __restrict__ W1, const float* __restrict__ b1v,
             const float* __restrict__ W2, const float* __restrict__ b2v,
             float* __restrict__ hout, const int* __restrict__ batch,
             int seg, int write_out) {
    extern __shared__ float sm[];
    float* As = sm;                 // TILE x AST (agg -> mid -> h/pool)
    float* Bs = sm + TILE * AST;    // 128 x 128 single weight buffer
    __shared__ int batchS[TILE];

    int tid = threadIdx.x, lane = tid & 31, wid = tid >> 5;
    int row0 = blockIdx.x * TILE;

    // stage W1 (overlaps with agg loads below)
    #pragma unroll
    for (int t = 0; t < 16; t++)
        ((float4*)Bs)[tid + t * 256] = ((const float4*)W1)[tid + t * 256];
    if (tid < TILE) { int r = row0 + tid; batchS[tid] = (r < N_NODESC) ? batch[r] : -1; }

    // aggregation: 8 warps x 8 rows, MLP-8 unroll
    const float4* xi = (const float4*)hin;
    for (int rr = wid; rr < TILE; rr += 8) {
        int row = row0 + rr;
        float4 a0 = make_float4(0.f, 0.f, 0.f, 0.f);
        float4 a1 = a0, a2 = a0, a3 = a0, a4 = a0, a5 = a0, a6 = a0, a7 = a0;
        if (row < N_NODESC) {
            a0 = xi[row * 32 + lane];
            int s0 = g_off[row], s1 = g_off[row + 1], j = s0;
            for (; j + 7 < s1; j += 8) {
                int i0 = g_srcs[j],     i1 = g_srcs[j + 1], i2 = g_srcs[j + 2], i3 = g_srcs[j + 3];
                int i4 = g_srcs[j + 4], i5 = g_srcs[j + 5], i6 = g_srcs[j + 6], i7 = g_srcs[j + 7];
                addf4(a0, xi[i0 * 32 + lane]); addf4(a1, xi[i1 * 32 + lane]);
                addf4(a2, xi[i2 * 32 + lane]); addf4(a3, xi[i3 * 32 + lane]);
                addf4(a4, xi[i4 * 32 + lane]); addf4(a5, xi[i5 * 32 + lane]);
                addf4(a6, xi[i6 * 32 + lane]); addf4(a7, xi[i7 * 32 + lane]);
            }
            for (; j + 1 < s1; j += 2) {
                addf4(a0, xi[g_srcs[j] * 32 + lane]);
                addf4(a1, xi[g_srcs[j + 1] * 32 + lane]);
            }
            if (j < s1) addf4(a0, xi[g_srcs[j] * 32 + lane]);
        }
        addf4(a0, a1); addf4(a2, a3); addf4(a4, a5); addf4(a6, a7);
        addf4(a0, a2); addf4(a4, a6); addf4(a0, a4);
        *(float4*)&As[rr * AST + lane * 4] = a0;
    }
    __syncthreads();

    int tx = tid & 15, ty = tid >> 4;
    int r0 = ty * 4, c0 = tx * 4;

    // GEMM1: mid = relu(agg @ W1 + b1)
    ull acc[4][4];
    #pragma unroll
    for (int i = 0; i < 4; i++) { acc[i][0] = acc[i][1] = acc[i][2] = acc[i][3] = 0ull; }
    gemm_tile(As, AST, Bs, 128, acc, r0, c0);
    __syncthreads();     // reads of As(agg) and Bs(W1) done
    #pragma unroll
    for (int i = 0; i < 4; i++) {
        float4 lo, hi;
        epi_relu(acc[i], b1v, c0, lo, hi);
        *(float4*)&As[(r0 + i) * AST + c0] = lo;
        *(float4*)&As[(r0 + i) * AST + c0 + 64] = hi;
    }
    // restage W2
    #pragma unroll
    for (int t = 0; t < 16; t++)
        ((float4*)Bs)[tid + t * 256] = ((const float4*)W2)[tid + t * 256];
    __syncthreads();

    // GEMM2: h = relu(mid @ W2 + b2)
    #pragma unroll
    for (int i = 0; i < 4; i++) { acc[i][0] = acc[i][1] = acc[i][2] = acc[i][3] = 0ull; }
    gemm_tile(As, AST, Bs, 128, acc, r0, c0);
    __syncthreads();     // reads of As(mid) done
    #pragma unroll
    for (int i = 0; i < 4; i++) {
        float4 lo, hi;
        epi_relu(acc[i], b2v, c0, lo, hi);
        int rr = r0 + i, row = row0 + rr;
        *(float4*)&As[rr * AST + c0] = lo;
        *(float4*)&As[rr * AST + c0 + 64] = hi;
        if (write_out && row < N_NODESC) {
            *(float4*)&hout[row * HC + c0] = lo;
            *(float4*)&hout[row * HC + c0 + 64] = hi;
        }
    }
    __syncthreads();
    pool_tile(As, batchS, seg, tid);
}

// ---------------- fused layer 1: agg8 + MLP(8->128->128) + pool ----------------
__global__ __launch_bounds__(256, 2)
void k_layer1(const float* __restrict__ x,
              const float* __restrict__ W1, const float* __restrict__ b1v,
              const float* __restrict__ W2, const float* __restrict__ b2v,
              float* __restrict__ hout, const int* __restrict__ batch) {
    extern __shared__ float sm[];
    float* As = sm;                         // TILE x AST
    float* Bs = sm + TILE * AST;            // 128 x 128 (W2)
    float* A8 = Bs + 128 * 128;             // TILE x 8
    float* B8 = A8 + TILE * 8;              // 8 x 128 (W1)
    __shared__ int batchS[TILE];

    int tid = threadIdx.x;
    int row0 = blockIdx.x * TILE;

    ((float4*)B8)[tid] = ((const float4*)W1)[tid & 255];
    #pragma unroll
    for (int t = 0; t < 16; t++)
        ((float4*)Bs)[tid + t * 256] = ((const float4*)W2)[tid + t * 256];
    if (tid < TILE) { int r = row0 + tid; batchS[tid] = (r < N_NODESC) ? batch[r] : -1; }

    // agg8: 2 threads per row (first 128 threads), MLP-4
    if (tid < 2 * TILE) {
        int row_l = tid >> 1, half = tid & 1, row = row0 + row_l;
        float4 a0 = make_float4(0.f, 0.f, 0.f, 0.f);
        float4 a1 = a0, a2 = a0, a3 = a0;
        if (row < N_NODESC) {
            const float4* x4 = (const float4*)x;
            a0 = x4[row * 2 + half];
            int s0 = g_off[row], s1 = g_off[row + 1], j = s0;
            for (; j + 3 < s1; j += 4) {
                addf4(a0, x4[g_srcs[j] * 2 + half]);
                addf4(a1, x4[g_srcs[j + 1] * 2 + half]);
                addf4(a2, x4[g_srcs[j + 2] * 2 + half]);
                addf4(a3, x4[g_srcs[j + 3] * 2 + half]);
            }
            for (; j < s1; j++) addf4(a0, x4[g_srcs[j] * 2 + half]);
        }
        addf4(a0, a1); addf4(a2, a3); addf4(a0, a2);
        *(float4*)&A8[row_l * 8 + half * 4] = a0;
    }
    __syncthreads();

    int tx = tid & 15, ty = tid >> 4;
    int r0 = ty * 4, c0 = tx * 4;

    // GEMM1 (K=8): mid = relu(agg8 @ W1 + b1) -> As
    ull acc[4][4];
    #pragma unroll
    for (int i = 0; i < 4; i++) { acc[i][0] = acc[i][1] = acc[i][2] = acc[i][3] = 0ull; }
    gemm_tile(A8, 8, B8, 8, acc, r0, c0);
    #pragma unroll
    for (int i = 0; i < 4; i++) {
        float4 lo, hi;
        epi_relu(acc[i], b1v, c0, lo, hi);
        *(float4*)&As[(r0 + i) * AST + c0] = lo;
        *(float4*)&As[(r0 + i) * AST + c0 + 64] = hi;
    }
    __syncthreads();

    // GEMM2: h1 = relu(mid @ W2 + b2)
    #pragma unroll
    for (int i = 0; i < 4; i++) { acc[i][0] = acc[i][1] = acc[i][2] = acc[i][3] = 0ull; }
    gemm_tile(As, AST, Bs, 128, acc, r0, c0);
    __syncthreads();
    #pragma unroll
    for (int i = 0; i < 4; i++) {
        float4 lo, hi;
        epi_relu(acc[i], b2v, c0, lo, hi);
        int rr = r0 + i, row = row0 + rr;
        *(float4*)&As[rr * AST + c0] = lo;
        *(float4*)&As[rr * AST + c0 + 64] = hi;
        if (row < N_NODESC) {
            *(float4*)&hout[row * HC + c0] = lo;
            *(float4*)&hout[row * HC + c0 + 64] = hi;
        }
    }
    __syncthreads();
    pool_tile(As, batchS, 0, tid);
}

// ---------------- classifier ----------------
__global__ void k_cls(const float* __restrict__ W1, const float* __restrict__ b1,
                      const float* __restrict__ bng, const float* __restrict__ bnb,
                      const float* __restrict__ bnm, const float* __restrict__ bnv,
                      const float* __restrict__ W2, const float* __restrict__ b2,
                      float* __restrict__ out) {
    __shared__ float ps[384];
    __shared__ float zs[256];
    int gph = blockIdx.x, tid = threadIdx.x;
    for (int i = tid; i < 384; i += 256) ps[i] = g_pooled[gph * 384 + i];
    __syncthreads();
    float acc = b1[tid];
    for (int k = 0; k < 384; k++) acc += ps[k] * W1[k * 256 + tid];
    acc = (acc - bnm[tid]) * rsqrtf(bnv[tid] + 1e-5f) * bng[tid] + bnb[tid];
    zs[tid] = fmaxf(acc, 0.f);
    __syncthreads();
    if (tid < 4) {
        float s = b2[tid];
        for (int k = 0; k < 256; k++) s += zs[k] * W2[k * 4 + tid];
        out[gph * 4 + tid] = s;
    }
}

// ---------------- launch ----------------
extern "C" void kernel_launch(void* const* d_in, const int* in_sizes, int n_in,
                              void* d_out, int out_size) {
    const float* x   = (const float*)d_in[0];
    const int* ei    = (const int*)d_in[1];
    const int* batch = (const int*)d_in[2];
    const float* l1W1 = (const float*)d_in[3];
    const float* l1b1 = (const float*)d_in[4];
    const float* l1W2 = (const float*)d_in[5];
    const float* l1b2 = (const float*)d_in[6];
    const float* l2W1 = (const float*)d_in[7];
    const float* l2b1 = (const float*)d_in[8];
    const float* l2W2 = (const float*)d_in[9];
    const float* l2b2 = (const float*)d_in[10];
    const float* l3W1 = (const float*)d_in[11];
    const float* l3b1 = (const float*)d_in[12];
    const float* l3W2 = (const float*)d_in[13];
    const float* l3b2 = (const float*)d_in[14];
    const float* cW1  = (const float*)d_in[15];
    const float* cb1  = (const float*)d_in[16];
    const float* bng  = (const float*)d_in[17];
    const float* bnb  = (const float*)d_in[18];
    const float* bnm  = (const float*)d_in[19];
    const float* bnv  = (const float*)d_in[20];
    const float* cW2  = (const float*)d_in[21];
    const float* cb2  = (const float*)d_in[22];
    float* out = (float*)d_out;

    float *h1, *h2;
    cudaGetSymbolAddress((void**)&h1, g_h1);
    cudaGetSymbolAddress((void**)&h2, g_h2);

    const int LAYER_SMEM  = (TILE * AST + 128 * 128) * 4;                       // 99328
    const int LAYER1_SMEM = LAYER_SMEM + (TILE * 8 + 8 * 128) * 4;              // 105472
    cudaFuncSetAttribute(k_layer,  cudaFuncAttributeMaxDynamicSharedMemorySize, LAYER_SMEM);
    cudaFuncSetAttribute(k_layer1, cudaFuncAttributeMaxDynamicSharedMemorySize, LAYER1_SMEM);

    const int blocks = (N_NODESC + TILE - 1) / TILE;   // 782

    k_init<<<(N_NODESC + 255) / 256, 256>>>();
    k_hist<<<(N_EDGESC / 4 + 255) / 256, 256>>>(ei);
    k_scan<<<1, 1024>>>();
    k_fill<<<(N_EDGESC / 4 + 255) / 256, 256>>>(ei);

    k_layer1<<<blocks, 256, LAYER1_SMEM>>>(x, l1W1, l1b1, l1W2, l1b2, h1, batch);
    k_layer<<<blocks, 256, LAYER_SMEM>>>(h1, l2W1, l2b1, l2W2, l2b2, h2, batch, 1, 1);
    k_layer<<<blocks, 256, LAYER_SMEM>>>(h2, l3W1, l3b1, l3W2, l3b2, h2, batch, 2, 0);

    k_cls<<<N_GRAPHSC, 256>>>(cW1, cb1, bng, bnb, bnm, bnv, cW2, cb2, out);
}